// round 13
// baseline (speedup 1.0000x reference)
#include <cuda_runtime.h>
typedef unsigned long long u64;
#define NB 16
#define NH 8

__device__ float g_m[NB * NH * 1024];        // tanh-MLP, [b][h][n]
__device__ float g_A[NB * NH * 4 * 128];     // per (b,h,chunk): A+[64], A-[64]
__device__ float g_ut[NB * NH * 2048];       // per (b,h): u[1024], t[1024]

__device__ __forceinline__ u64 pack2(float a, float b) {
    u64 r; asm("mov.b64 %0,{%1,%2};" : "=l"(r) : "f"(a), "f"(b)); return r;
}
__device__ __forceinline__ void fma2(u64& d, u64 a, u64 b) {
    asm("fma.rn.f32x2 %0,%1,%2,%0;" : "+l"(d) : "l"(a), "l"(b));
}
__device__ __forceinline__ float2 unpack2(u64 v) {
    float2 r; asm("mov.b64 {%0,%1},%2;" : "=f"(r.x), "=f"(r.y) : "l"(v)); return r;
}
__device__ __forceinline__ unsigned su32(const void* p) {
    unsigned r;
    asm("{.reg .u64 t; cvta.to.shared.u64 t,%1; cvt.u32.u64 %0,t;}" : "=r"(r) : "l"(p));
    return r;
}
#define CP16(d, s) asm volatile("cp.async.cg.shared.global [%0],[%1],16;" :: "r"(d), "l"(s))
#define CPC()      asm volatile("cp.async.commit_group;")

// ---------- k1: MLP m = tanh(x@W^T + b); thread = (row, h); x via cp.async+LDS bcast ----
// dyn smem floats: sw @0 [8][1028], sx @8224 [2][32][132], sb @16672 [8]  (66720 B)
__global__ void __launch_bounds__(256) k1_mlp(const float* __restrict__ x,
                                              const float* __restrict__ w,
                                              const float* __restrict__ bias) {
    extern __shared__ __align__(16) float SM1[];
    float* sw = SM1;
    float* sx = SM1 + 8224;
    float* sb = SM1 + 16672;
    const int tid = threadIdx.x;

    // load W padded [8][1028]
    for (int i = tid; i < 2048; i += 256) {
        int hh = i >> 8, kk = (i & 255) << 2;
        *(float4*)&sw[hh * 1028 + kk] = ((const float4*)w)[i];
    }
    if (tid < 8) sb[tid] = bias[tid];

    const int row0 = blockIdx.x * 32;
    const unsigned sxb = su32(SM1) + 8224u * 4u;

    // prologue: stage chunk 0 into buf 0 (32 rows x 128 cols)
#pragma unroll
    for (int i = 0; i < 4; ++i) {
        int s = tid + i * 256;
        int r = s >> 5, c16 = s & 31;
        CP16(sxb + (unsigned)(r * 132 + c16 * 4) * 4u,
             x + (long)(row0 + r) * 1024 + c16 * 4);
    }
    CPC();

    const int h = tid & 7, rr = tid >> 3;
    u64 a0 = 0ull, a1 = 0ull;

    for (int c = 0; c < 8; ++c) {
        int buf = c & 1;
        if (c < 7) {
            int nb = buf ^ 1;
#pragma unroll
            for (int i = 0; i < 4; ++i) {
                int s = tid + i * 256;
                int r = s >> 5, c16 = s & 31;
                CP16(sxb + (unsigned)(nb * 4224 + r * 132 + c16 * 4) * 4u,
                     x + (long)(row0 + r) * 1024 + (c + 1) * 128 + c16 * 4);
            }
            CPC();
            asm volatile("cp.async.wait_group 1;");
        } else {
            asm volatile("cp.async.wait_group 0;");
        }
        __syncthreads();   // chunk c visible to all (also covers sw on c==0)

        const float* xr = sx + buf * 4224 + rr * 132;
        const float* wr = sw + h * 1028 + c * 128;
#pragma unroll 8
        for (int kk = 0; kk < 128; kk += 4) {
            fma2(a0, *(const u64*)&xr[kk],     *(const u64*)&wr[kk]);
            fma2(a1, *(const u64*)&xr[kk + 2], *(const u64*)&wr[kk + 2]);
        }
        __syncthreads();   // compute done before buf is re-staged (c+2)
    }

    float2 p0 = unpack2(a0), p1 = unpack2(a1);
    float v = tanhf(p0.x + p0.y + p1.x + p1.y + sb[h]);
    int row = row0 + rr;
    int b = row >> 10, j = row & 1023;
    g_m[(b * 8 + (j >> 7)) * 1024 + ((j & 127) << 3) + h] = v;
}

// ---------- k2_A: partial A+/-[e] over 256-n chunks ----------
__global__ void __launch_bounds__(256) k2_A(const float* __restrict__ Q) {
    int chunk = blockIdx.x, h = blockIdx.y, b = blockIdx.z;
    int tid = threadIdx.x;
    int e = tid & 63, st = tid >> 6;
    int n0 = chunk * 256 + st * 64;
    const float* mp = g_m + (b * 8 + h) * 1024 + n0;
    const float* qp = Q + ((long)(b * 1024 + n0) * 8 + h) * 64 + e;
    float ap = 0.f, an = 0.f;
#pragma unroll 8
    for (int n = 0; n < 64; ++n) {
        float m = mp[n];
        float qv = qp[(long)n * 512];
        ap += fmaxf(m, 0.f) * qv;
        an += fminf(m, 0.f) * qv;
    }
    __shared__ float sp[4][64], sn[4][64];
    sp[st][e] = ap; sn[st][e] = an;
    __syncthreads();
    long base = ((long)(b * 8 + h) * 4 + chunk) * 128;
    if (tid < 64)
        g_A[base + tid] = sp[0][tid] + sp[1][tid] + sp[2][tid] + sp[3][tid];
    else if (tid < 128) {
        int e2 = tid & 63;
        g_A[base + 64 + e2] = sn[0][e2] + sn[1][e2] + sn[2][e2] + sn[3][e2];
    }
}

// ---------- k2_ut: u[s] = K[s]·A+, t[s] = K[s]·A- ----------
__global__ void __launch_bounds__(256) k2_ut(const float* __restrict__ K) {
    int chunk = blockIdx.x, h = blockIdx.y, b = blockIdx.z;
    int tid = threadIdx.x, warp = tid >> 5, lane = tid & 31;
    int sg = lane >> 3, le = lane & 7;
    __shared__ float sA[128];
    if (tid < 128) {
        const float* Ab = g_A + (long)(b * 8 + h) * 512 + tid;
        sA[tid] = Ab[0] + Ab[128] + Ab[256] + Ab[384];
    }
    __syncthreads();
    float rAp[8], rAn[8];
#pragma unroll
    for (int i = 0; i < 8; ++i) { rAp[i] = sA[le * 8 + i]; rAn[i] = sA[64 + le * 8 + i]; }

    const float* Kb = K + ((long)b * 8192 + h) * 64;
    float* utb = g_ut + (long)(b * 8 + h) * 2048;
#pragma unroll 4
    for (int p = 0; p < 4; ++p) {
        int s = chunk * 128 + p * 32 + warp * 4 + sg;
        const float* kr = Kb + (long)s * 512 + le * 8;
        float4 k0 = *(const float4*)kr;
        float4 k1 = *(const float4*)(kr + 4);
        float kv[8] = {k0.x, k0.y, k0.z, k0.w, k1.x, k1.y, k1.z, k1.w};
        float u = 0.f, t = 0.f;
#pragma unroll
        for (int i = 0; i < 8; ++i) { u += kv[i] * rAp[i]; t += kv[i] * rAn[i]; }
#pragma unroll
        for (int off = 1; off < 8; off <<= 1) {
            u += __shfl_xor_sync(0xffffffffu, u, off);
            t += __shfl_xor_sync(0xffffffffu, t, off);
        }
        if (le == 0) { utb[s] = u; utb[1024 + s] = t; }
    }
}

// ---------- k3: softmax from (u,t), out[e,g] = sum_s V[s,e] P[s,g]  (R9 exact) ----------
__global__ void __launch_bounds__(256, 1) k3_attn(const float* __restrict__ V,
                                                  const float* __restrict__ sW,
                                                  float* __restrict__ out) {
    __shared__ __align__(16) float SM[10752];
    const int h = blockIdx.x, b = blockIdx.y, tid = threadIdx.x;
    const unsigned smb = su32(SM);
    const int part = tid & 7, sl = tid >> 3;
    const int quarter = tid >> 6, eg = (tid >> 3) & 7, gg = tid & 7;

    {
        const float4* utb = (const float4*)(g_ut + (long)(b * 8 + h) * 2048);
        float4* d = (float4*)(SM + 8704);
        d[tid] = utb[tid];
        d[256 + tid] = utb[256 + tid];
    }
    float ra[8], rc[8];
#pragma unroll
    for (int j = 0; j < 8; ++j) {
        float w = sW[h * 64 + part * 8 + j];
        ra[j] = 0.125f * fmaxf(w, 0.f);
        rc[j] = 0.125f * fminf(w, 0.f);
    }

    const float* Vb = V + ((long)b * 8192 + h) * 64;
#pragma unroll
    for (int i = 0; i < 2; ++i) {
        int idx = i * 256 + tid;
        int row = idx >> 4, col = (idx & 15) << 2;
        CP16(smb + (((unsigned)(row * 68 + col)) << 2), Vb + (long)row * 512 + col);
    }
    CPC();
    __syncthreads();

    u64 acc[32];
#pragma unroll
    for (int i = 0; i < 32; ++i) acc[i] = 0ull;

    for (int t = 0; t < 32; ++t) {
        int buf = t & 1;
        asm volatile("cp.async.wait_group 0;");

        float* sP = SM + 4352 + buf * 2176;
        {
            int s = t * 32 + sl;
            float u = SM[8704 + s], tt = SM[9728 + s];
            float l[8], mx = -1e30f;
#pragma unroll
            for (int j = 0; j < 8; ++j) { l[j] = u * ra[j] + tt * rc[j]; mx = fmaxf(mx, l[j]); }
#pragma unroll
            for (int off = 1; off < 8; off <<= 1)
                mx = fmaxf(mx, __shfl_xor_sync(0xffffffffu, mx, off));
            float sum = 0.f;
#pragma unroll
            for (int j = 0; j < 8; ++j) { l[j] = __expf(l[j] - mx); sum += l[j]; }
#pragma unroll
            for (int off = 1; off < 8; off <<= 1)
                sum += __shfl_xor_sync(0xffffffffu, sum, off);
            float inv = __fdividef(1.f, sum);
            *(float4*)&sP[sl * 68 + part * 8]     = make_float4(l[0] * inv, l[1] * inv, l[2] * inv, l[3] * inv);
            *(float4*)&sP[sl * 68 + part * 8 + 4] = make_float4(l[4] * inv, l[5] * inv, l[6] * inv, l[7] * inv);
        }
        __syncthreads();

        if (t + 1 < 32) {
            int s0 = (t + 1) * 32, nb = buf ^ 1;
#pragma unroll
            for (int i = 0; i < 2; ++i) {
                int idx = i * 256 + tid;
                int row = idx >> 4, col = (idx & 15) << 2;
                CP16(smb + (((unsigned)(nb * 2176 + row * 68 + col)) << 2),
                     Vb + (long)(s0 + row) * 512 + col);
            }
            CPC();
        } else {
            CPC();
        }

        const float* vb = SM + buf * 2176;
#pragma unroll
        for (int s8 = 0; s8 < 8; ++s8) {
            int sq = quarter * 8 + s8;
            float4 v0 = *(const float4*)&vb[sq * 68 + eg * 8];
            float4 v1 = *(const float4*)&vb[sq * 68 + eg * 8 + 4];
            ulonglong2 pA = *(const ulonglong2*)&sP[sq * 68 + gg * 8];
            ulonglong2 pB = *(const ulonglong2*)&sP[sq * 68 + gg * 8 + 4];
            float ve[8] = {v0.x, v0.y, v0.z, v0.w, v1.x, v1.y, v1.z, v1.w};
#pragma unroll
            for (int e = 0; e < 8; ++e) {
                u64 vv = pack2(ve[e], ve[e]);
                fma2(acc[e * 4 + 0], vv, pA.x);
                fma2(acc[e * 4 + 1], vv, pA.y);
                fma2(acc[e * 4 + 2], vv, pB.x);
                fma2(acc[e * 4 + 3], vv, pB.y);
            }
        }
    }

    u64* sred = (u64*)SM;
    __syncthreads();
    if (tid >= 128) {
        int j = tid - 128;
#pragma unroll
        for (int i = 0; i < 32; ++i) sred[j * 32 + i] = acc[i];
    }
    __syncthreads();
    if (tid < 128) {
#pragma unroll
        for (int i = 0; i < 32; ++i) {
            float2 a = unpack2(acc[i]), c = unpack2(sred[tid * 32 + i]);
            acc[i] = pack2(a.x + c.x, a.y + c.y);
        }
    }
    __syncthreads();
    if (tid >= 64 && tid < 128) {
#pragma unroll
        for (int i = 0; i < 32; ++i) sred[(tid - 64) * 32 + i] = acc[i];
    }
    __syncthreads();
    if (tid < 64) {
#pragma unroll
        for (int i = 0; i < 32; ++i) {
            float2 a = unpack2(acc[i]), c = unpack2(sred[tid * 32 + i]);
            acc[i] = pack2(a.x + c.x, a.y + c.y);
        }
#pragma unroll
        for (int e = 0; e < 8; ++e) {
            long ob = ((long)(b * 64 + eg * 8 + e) * 8 + h) * 64 + gg * 8;
            float2 p0 = unpack2(acc[e * 4 + 0]), p1 = unpack2(acc[e * 4 + 1]);
            float2 p2 = unpack2(acc[e * 4 + 2]), p3 = unpack2(acc[e * 4 + 3]);
            *(float4*)&out[ob]     = make_float4(p0.x, p0.y, p1.x, p1.y);
            *(float4*)&out[ob + 4] = make_float4(p2.x, p2.y, p3.x, p3.y);
        }
    }
}

extern "C" void kernel_launch(void* const* d_in, const int* in_sizes, int n_in,
                              void* d_out, int out_size) {
    const float* q  = (const float*)d_in[0];
    const float* k  = (const float*)d_in[1];
    const float* v  = (const float*)d_in[2];
    const float* x  = (const float*)d_in[3];
    const float* mw = (const float*)d_in[4];
    const float* mb = (const float*)d_in[5];
    const float* sW = (const float*)d_in[6];
    (void)in_sizes; (void)n_in; (void)out_size;
    float* out = (float*)d_out;

    cudaFuncSetAttribute(k1_mlp, cudaFuncAttributeMaxDynamicSharedMemorySize, 66816);

    k1_mlp<<<512, 256, 66816>>>(x, mw, mb);
    k2_A<<<dim3(4, NH, NB), 256>>>(q);
    k2_ut<<<dim3(8, NH, NB), 256>>>(k);
    k3_attn<<<dim3(NH, NB), 256>>>(v, sW, out);
}

// round 14
// speedup vs baseline: 1.2855x; 1.2855x over previous
#include <cuda_runtime.h>
typedef unsigned long long u64;
#define NB 16
#define NH 8

__device__ float g_m[NB * NH * 1024];        // tanh-MLP, [b][h][n]
__device__ float g_A[NB * NH * 8 * 128];     // per (b,h,chunk): A+[64], A-[64]
__device__ float g_ut[NB * NH * 2048];       // per (b,h): u[1024], t[1024]

__device__ __forceinline__ u64 pack2(float a, float b) {
    u64 r; asm("mov.b64 %0,{%1,%2};" : "=l"(r) : "f"(a), "f"(b)); return r;
}
__device__ __forceinline__ void fma2(u64& d, u64 a, u64 b) {
    asm("fma.rn.f32x2 %0,%1,%2,%0;" : "+l"(d) : "l"(a), "l"(b));
}
__device__ __forceinline__ float2 unpack2(u64 v) {
    float2 r; asm("mov.b64 {%0,%1},%2;" : "=f"(r.x), "=f"(r.y) : "l"(v)); return r;
}
__device__ __forceinline__ unsigned su32(const void* p) {
    unsigned r;
    asm("{.reg .u64 t; cvta.to.shared.u64 t,%1; cvt.u32.u64 %0,t;}" : "=r"(r) : "l"(p));
    return r;
}
#define CP16(d, s) asm volatile("cp.async.cg.shared.global [%0],[%1],16;" :: "r"(d), "l"(s))
#define CPC()      asm volatile("cp.async.commit_group;")

// ---------- k1: MLP m = tanh(x@W^T + b); warp = 4 rows x 8 heads, k-pair FMA2 ----------
__global__ void __launch_bounds__(256) k1_mlp(const float* __restrict__ x,
                                              const float* __restrict__ w,
                                              const float* __restrict__ bias) {
    __shared__ __align__(16) float sw[8 * 1024];
    __shared__ float sb[8];
    int tid = threadIdx.x;
    for (int i = tid; i < 2048; i += 256)
        ((float4*)sw)[i] = ((const float4*)w)[i];
    if (tid < 8) sb[tid] = bias[tid];
    __syncthreads();

    int warp = tid >> 5, lane = tid & 31;
    int row0 = blockIdx.x * 32 + warp * 4;
    const float4* x0 = (const float4*)(x + (long)row0 * 1024);

    u64 acc2[4][8];
#pragma unroll
    for (int r = 0; r < 4; ++r)
#pragma unroll
        for (int h = 0; h < 8; ++h) acc2[r][h] = 0ull;

#pragma unroll 2
    for (int j = 0; j < 8; ++j) {
        float4 xv[4];
#pragma unroll
        for (int r = 0; r < 4; ++r) xv[r] = x0[r * 256 + j * 32 + lane];
        u64 xp[4][2];
#pragma unroll
        for (int r = 0; r < 4; ++r) {
            xp[r][0] = pack2(xv[r].x, xv[r].y);
            xp[r][1] = pack2(xv[r].z, xv[r].w);
        }
#pragma unroll
        for (int h = 0; h < 8; ++h) {
            float4 wv = *(const float4*)&sw[h * 1024 + lane * 4 + j * 128];
            u64 w01 = pack2(wv.x, wv.y), w23 = pack2(wv.z, wv.w);
#pragma unroll
            for (int r = 0; r < 4; ++r) {
                fma2(acc2[r][h], xp[r][0], w01);
                fma2(acc2[r][h], xp[r][1], w23);
            }
        }
    }

    float acc[4][8];
#pragma unroll
    for (int r = 0; r < 4; ++r)
#pragma unroll
        for (int h = 0; h < 8; ++h) {
            float2 p = unpack2(acc2[r][h]);
            acc[r][h] = p.x + p.y;
        }

#pragma unroll
    for (int r = 0; r < 4; ++r)
#pragma unroll
        for (int h = 0; h < 8; ++h)
#pragma unroll
            for (int off = 16; off > 0; off >>= 1)
                acc[r][h] += __shfl_xor_sync(0xffffffffu, acc[r][h], off);

    float sel = 0.f;
#pragma unroll
    for (int r = 0; r < 4; ++r)
#pragma unroll
        for (int h = 0; h < 8; ++h)
            if (lane == r * 8 + h) sel = acc[r][h];

    int hh = lane & 7;
    int row = row0 + (lane >> 3);
    float v = tanhf(sel + sb[hh]);
    int b = row >> 10, j = row & 1023;
    g_m[(b * 8 + (j >> 7)) * 1024 + ((j & 127) << 3) + hh] = v;
}

// ---------- k2_A: partial A+/-[e] over 128-n chunks (8 chunks) ----------
__global__ void __launch_bounds__(256) k2_A(const float* __restrict__ Q) {
    int chunk = blockIdx.x, h = blockIdx.y, b = blockIdx.z;
    int tid = threadIdx.x;
    int e = tid & 63, st = tid >> 6;
    int n0 = chunk * 128 + st * 32;
    const float* mp = g_m + (b * 8 + h) * 1024 + n0;
    const float* qp = Q + ((long)(b * 1024 + n0) * 8 + h) * 64 + e;
    float ap = 0.f, an = 0.f;
#pragma unroll 8
    for (int n = 0; n < 32; ++n) {
        float m = mp[n];
        float qv = qp[(long)n * 512];
        ap += fmaxf(m, 0.f) * qv;
        an += fminf(m, 0.f) * qv;
    }
    __shared__ float sp[4][64], sn[4][64];
    sp[st][e] = ap; sn[st][e] = an;
    __syncthreads();
    long base = ((long)(b * 8 + h) * 8 + chunk) * 128;
    if (tid < 64)
        g_A[base + tid] = sp[0][tid] + sp[1][tid] + sp[2][tid] + sp[3][tid];
    else if (tid < 128) {
        int e2 = tid & 63;
        g_A[base + 64 + e2] = sn[0][e2] + sn[1][e2] + sn[2][e2] + sn[3][e2];
    }
}

// ---------- k2_ut: u[s] = K[s]·A+, t[s] = K[s]·A- ----------
__global__ void __launch_bounds__(256) k2_ut(const float* __restrict__ K) {
    int chunk = blockIdx.x, h = blockIdx.y, b = blockIdx.z;
    int tid = threadIdx.x, warp = tid >> 5, lane = tid & 31;
    int sg = lane >> 3, le = lane & 7;
    __shared__ float sA[128];
    if (tid < 128) {
        const float* Ab = g_A + (long)(b * 8 + h) * 1024 + tid;
        float s = 0.f;
#pragma unroll
        for (int c = 0; c < 8; ++c) s += Ab[c * 128];
        sA[tid] = s;
    }
    __syncthreads();
    float rAp[8], rAn[8];
#pragma unroll
    for (int i = 0; i < 8; ++i) { rAp[i] = sA[le * 8 + i]; rAn[i] = sA[64 + le * 8 + i]; }

    const float* Kb = K + ((long)b * 8192 + h) * 64;
    float* utb = g_ut + (long)(b * 8 + h) * 2048;
#pragma unroll 4
    for (int p = 0; p < 4; ++p) {
        int s = chunk * 128 + p * 32 + warp * 4 + sg;
        const float* kr = Kb + (long)s * 512 + le * 8;
        float4 k0 = *(const float4*)kr;
        float4 k1 = *(const float4*)(kr + 4);
        float kv[8] = {k0.x, k0.y, k0.z, k0.w, k1.x, k1.y, k1.z, k1.w};
        float u = 0.f, t = 0.f;
#pragma unroll
        for (int i = 0; i < 8; ++i) { u += kv[i] * rAp[i]; t += kv[i] * rAn[i]; }
#pragma unroll
        for (int off = 1; off < 8; off <<= 1) {
            u += __shfl_xor_sync(0xffffffffu, u, off);
            t += __shfl_xor_sync(0xffffffffu, t, off);
        }
        if (le == 0) { utb[s] = u; utb[1024 + s] = t; }
    }
}

// ---------- k3: 64 s per iteration (16 iters), 1 barrier per iter ----------
// dyn SM floats: sV[2][64*68]=8704 @0, sP[64*68]=4352 @8704, u@13056, t@14080 (15104 fl)
__global__ void __launch_bounds__(256, 1) k3_attn(const float* __restrict__ V,
                                                  const float* __restrict__ sW,
                                                  float* __restrict__ out) {
    extern __shared__ __align__(16) float SM[];
    const int h = blockIdx.x, b = blockIdx.y, tid = threadIdx.x;
    const unsigned smb = su32(SM);
    const int part = tid & 7, sl = tid >> 3;
    const int quarter = tid >> 6, eg = (tid >> 3) & 7, gg = tid & 7;
    float* sP = SM + 8704;

    {   // load u,t (2048 floats)
        const float4* utb = (const float4*)(g_ut + (long)(b * 8 + h) * 2048);
        float4* d = (float4*)(SM + 13056);
        d[tid] = utb[tid];
        d[256 + tid] = utb[256 + tid];
    }
    float ra[8], rc[8];
#pragma unroll
    for (int j = 0; j < 8; ++j) {
        float w = sW[h * 64 + part * 8 + j];
        ra[j] = 0.125f * fmaxf(w, 0.f);
        rc[j] = 0.125f * fminf(w, 0.f);
    }

    const float* Vb = V + ((long)b * 8192 + h) * 64;
    // prologue: stage 64-row tile 0 into buffer 0 (1024 float4)
#pragma unroll
    for (int i = 0; i < 4; ++i) {
        int idx = i * 256 + tid;
        int row = idx >> 4, col = (idx & 15) << 2;
        CP16(smb + (((unsigned)(row * 68 + col)) << 2), Vb + (long)row * 512 + col);
    }
    CPC();
    __syncthreads();   // u,t visible

    u64 acc[32];
#pragma unroll
    for (int i = 0; i < 32; ++i) acc[i] = 0ull;

    for (int t = 0; t < 16; ++t) {
        int buf = t & 1;
        asm volatile("cp.async.wait_group 0;");

        // softmax for rows s0=t*64+sl and s0+32
#pragma unroll
        for (int half = 0; half < 2; ++half) {
            int s = t * 64 + half * 32 + sl;
            float u = SM[13056 + s], tt = SM[14080 + s];
            float l[8], mx = -1e30f;
#pragma unroll
            for (int j = 0; j < 8; ++j) { l[j] = u * ra[j] + tt * rc[j]; mx = fmaxf(mx, l[j]); }
#pragma unroll
            for (int off = 1; off < 8; off <<= 1)
                mx = fmaxf(mx, __shfl_xor_sync(0xffffffffu, mx, off));
            float sum = 0.f;
#pragma unroll
            for (int j = 0; j < 8; ++j) { l[j] = __expf(l[j] - mx); sum += l[j]; }
#pragma unroll
            for (int off = 1; off < 8; off <<= 1)
                sum += __shfl_xor_sync(0xffffffffu, sum, off);
            float inv = __fdividef(1.f, sum);
            float* row = &sP[(half * 32 + sl) * 68 + part * 8];
            *(float4*)row       = make_float4(l[0] * inv, l[1] * inv, l[2] * inv, l[3] * inv);
            *(float4*)(row + 4) = make_float4(l[4] * inv, l[5] * inv, l[6] * inv, l[7] * inv);
        }
        __syncthreads();   // sV[buf] landed for all; sP visible; prev phase B done

        // prefetch next 64-row tile into buf^1
        if (t + 1 < 16) {
            int s0 = (t + 1) * 64, nb = buf ^ 1;
#pragma unroll
            for (int i = 0; i < 4; ++i) {
                int idx = i * 256 + tid;
                int row = idx >> 4, col = (idx & 15) << 2;
                CP16(smb + (((unsigned)(nb * 4352 + row * 68 + col)) << 2),
                     Vb + (long)(s0 + row) * 512 + col);
            }
            CPC();
        } else {
            CPC();
        }

        // phase B: quarter covers full 64x64 over its 16 s
        const float* vb = SM + buf * 4352;
#pragma unroll
        for (int s16 = 0; s16 < 16; ++s16) {
            int sq = quarter * 16 + s16;
            float4 v0 = *(const float4*)&vb[sq * 68 + eg * 8];
            float4 v1 = *(const float4*)&vb[sq * 68 + eg * 8 + 4];
            ulonglong2 pA = *(const ulonglong2*)&sP[sq * 68 + gg * 8];
            ulonglong2 pB = *(const ulonglong2*)&sP[sq * 68 + gg * 8 + 4];
            float ve[8] = {v0.x, v0.y, v0.z, v0.w, v1.x, v1.y, v1.z, v1.w};
#pragma unroll
            for (int e = 0; e < 8; ++e) {
                u64 vv = pack2(ve[e], ve[e]);
                fma2(acc[e * 4 + 0], vv, pA.x);
                fma2(acc[e * 4 + 1], vv, pA.y);
                fma2(acc[e * 4 + 2], vv, pB.x);
                fma2(acc[e * 4 + 3], vv, pB.y);
            }
        }
        __syncthreads();   // phase B done before sP is overwritten next iter
    }

    // reduce 4 quarter-copies via smem, then store
    u64* sred = (u64*)SM;
    if (tid >= 128) {
        int j = tid - 128;
#pragma unroll
        for (int i = 0; i < 32; ++i) sred[j * 32 + i] = acc[i];
    }
    __syncthreads();
    if (tid < 128) {
#pragma unroll
        for (int i = 0; i < 32; ++i) {
            float2 a = unpack2(acc[i]), c = unpack2(sred[tid * 32 + i]);
            acc[i] = pack2(a.x + c.x, a.y + c.y);
        }
    }
    __syncthreads();
    if (tid >= 64 && tid < 128) {
#pragma unroll
        for (int i = 0; i < 32; ++i) sred[(tid - 64) * 32 + i] = acc[i];
    }
    __syncthreads();
    if (tid < 64) {
#pragma unroll
        for (int i = 0; i < 32; ++i) {
            float2 a = unpack2(acc[i]), c = unpack2(sred[tid * 32 + i]);
            acc[i] = pack2(a.x + c.x, a.y + c.y);
        }
#pragma unroll
        for (int e = 0; e < 8; ++e) {
            long ob = ((long)(b * 64 + eg * 8 + e) * 8 + h) * 64 + gg * 8;
            float2 p0 = unpack2(acc[e * 4 + 0]), p1 = unpack2(acc[e * 4 + 1]);
            float2 p2 = unpack2(acc[e * 4 + 2]), p3 = unpack2(acc[e * 4 + 3]);
            *(float4*)&out[ob]     = make_float4(p0.x, p0.y, p1.x, p1.y);
            *(float4*)&out[ob + 4] = make_float4(p2.x, p2.y, p3.x, p3.y);
        }
    }
}

extern "C" void kernel_launch(void* const* d_in, const int* in_sizes, int n_in,
                              void* d_out, int out_size) {
    const float* q  = (const float*)d_in[0];
    const float* k  = (const float*)d_in[1];
    const float* v  = (const float*)d_in[2];
    const float* x  = (const float*)d_in[3];
    const float* mw = (const float*)d_in[4];
    const float* mb = (const float*)d_in[5];
    const float* sW = (const float*)d_in[6];
    (void)in_sizes; (void)n_in; (void)out_size;
    float* out = (float*)d_out;

    cudaFuncSetAttribute(k3_attn, cudaFuncAttributeMaxDynamicSharedMemorySize, 15104 * 4);

    k1_mlp<<<512, 256>>>(x, mw, mb);
    k2_A<<<dim3(8, NH, NB), 256>>>(q);
    k2_ut<<<dim3(8, NH, NB), 256>>>(k);
    k3_attn<<<dim3(NH, NB), 256, 15104 * 4>>>(v, sW, out);
}